// round 7
// baseline (speedup 1.0000x reference)
#include <cuda_runtime.h>
#include <cstdint>

#define B_DIM 256
#define N_DIM 64
#define T_DIM 4096
#define H_DIM 16
#define TS    256   // t-tile per CTA
#define CH    64    // t-chunk width (4 chunks per tile)
#define SBC   72    // x chunk SMEM row stride (floats)
#define SW    68    // w SMEM row stride (floats)
#define SLOTS 18    // 18 slots x 16 CTAs = 288 CTAs (<= 296 co-resident)

// Scratch (device globals — no allocation allowed)
__device__ float2   g_part[B_DIM * 16 * N_DIM];  // per (b,tile,row): {sum, sumsq}
__device__ unsigned g_cnt[B_DIM];

// ======================= helpers =======================
__device__ __forceinline__ uint32_t smem_u32(const void* p) {
    uint32_t a;
    asm("{ .reg .u64 t; cvta.to.shared.u64 t, %1; cvt.u32.u64 %0, t; }" : "=r"(a) : "l"(p));
    return a;
}
__device__ __forceinline__ void cp16(uint32_t smem_dst, const void* gsrc) {
    asm volatile("cp.async.cg.shared.global [%0], [%1], 16;" :: "r"(smem_dst), "l"(gsrc) : "memory");
}
#define CP_COMMIT() asm volatile("cp.async.commit_group;" ::: "memory")
#define CP_WAIT0()  asm volatile("cp.async.wait_group 0;" ::: "memory")

__device__ __forceinline__ unsigned ld_acq(const unsigned* p) {
    unsigned v;
    asm volatile("ld.acquire.gpu.global.u32 %0, [%1];" : "=r"(v) : "l"(p) : "memory");
    return v;
}
__device__ __forceinline__ uint32_t f2tf32(float f) {
    uint32_t r;
    asm("cvt.rna.tf32.f32 %0, %1;" : "=r"(r) : "f"(f));
    return r;
}
__device__ __forceinline__ void mma_tf32(float& d0, float& d1, float& d2, float& d3,
                                         uint32_t a0, uint32_t a1, uint32_t a2, uint32_t a3,
                                         uint32_t b0, uint32_t b1) {
    asm volatile(
        "mma.sync.aligned.m16n8k8.row.col.f32.tf32.tf32.f32 "
        "{%0,%1,%2,%3},{%4,%5,%6,%7},{%8,%9},{%0,%1,%2,%3};"
        : "+f"(d0), "+f"(d1), "+f"(d2), "+f"(d3)
        : "r"(a0), "r"(a1), "r"(a2), "r"(a3), "r"(b0), "r"(b1));
}

// ---------------------------------------------------------------------------
// Counter reset (runs first every launch; graph-replay safe).
// ---------------------------------------------------------------------------
__global__ void zero_kernel() {
    g_cnt[threadIdx.x] = 0u;
}

// ---------------------------------------------------------------------------
// Fused persistent kernel. Grid = 288 CTAs (fully co-resident: 2/SM x 148).
// Slot s (16 CTAs, one per t-tile) processes batches s, s+18, ...
// Per batch: cp.async x tile -> per-row partial var sums -> publish+arrive ->
// spin for 16 siblings -> in-CTA energies + rank-1 softmax weights (tile 0
// writes attn_w) -> tf32 MMA GEMM + fp32 residual from the SAME SMEM tile.
// Next batch's chunk loads are issued as each chunk's buffer frees.
// ---------------------------------------------------------------------------
__global__ __launch_bounds__(256, 2) void fused_kernel(const float* __restrict__ x,
                                                       const float* __restrict__ Wq,
                                                       const float* __restrict__ bq,
                                                       const float* __restrict__ Wk,
                                                       const float* __restrict__ bk,
                                                       float* __restrict__ out,
                                                       float* __restrict__ attn_out) {
    extern __shared__ float smem[];
    float* xs  = smem;                       // 4 x [64][SBC]
    float* ws  = smem + 4 * N_DIM * SBC;     // [64][SW]
    float* e_s = ws + N_DIM * SW;            // [64]

    int slot = blockIdx.x >> 4;
    int tile = blockIdx.x & 15;
    int tid  = threadIdx.x;
    int wid  = tid >> 5;
    int lane = tid & 31;

    // Rank-1 logit coefficients (batch-independent), computed once.
    float c0 = 0.f, c1 = 0.f, c2 = 0.f, c3 = 0.f;
#pragma unroll
    for (int h = 0; h < H_DIM; h++) {
        float wq = __ldg(Wq + h), bqh = __ldg(bq + h);
        float wk = __ldg(Wk + h), bkh = __ldg(bk + h);
        c0 = fmaf(wq, wk, c0);
        c1 = fmaf(wq, bkh, c1);
        c2 = fmaf(bqh, wk, c2);
        c3 = fmaf(bqh, bkh, c3);
    }

    int ih = wid & 1;          // i half: rows [ih*32, +32)
    int tq = wid >> 1;         // t quarter within chunk: [tq*16, +16)
    int i0 = ih * 32;
    int r  = lane >> 2;        // 0..7
    int c  = lane & 3;         // 0..3

    // Prologue: issue all 4 chunk loads for first batch.
    {
        const float* xb = x + (size_t)slot * N_DIM * T_DIM + (size_t)tile * TS;
#pragma unroll
        for (int ch = 0; ch < 4; ch++) {
            float* xc = xs + ch * N_DIM * SBC;
#pragma unroll
            for (int k = 0; k < 4; k++) {
                int f  = k * 256 + tid;
                int jj = f >> 4;
                int c4 = f & 15;
                cp16(smem_u32(xc + jj * SBC + c4 * 4),
                     xb + (size_t)jj * T_DIM + ch * CH + c4 * 4);
            }
            CP_COMMIT();
        }
    }

    for (int b = slot; b < B_DIM; b += SLOTS) {
        int nb = b + SLOTS;
        CP_WAIT0();
        __syncthreads();

        // ---- Phase 1: per-row partial sums over this tile's 256 t-cols ----
        {
            int j = tid >> 2, k = tid & 3;
            float s = 0.f, ss = 0.f;
#pragma unroll
            for (int ch = 0; ch < 4; ch++) {
                const float* base = xs + ch * N_DIM * SBC + j * SBC + k * 16;
#pragma unroll
                for (int q = 0; q < 4; q++) {
                    float4 v = *reinterpret_cast<const float4*>(base + q * 4);
                    s  += (v.x + v.y) + (v.z + v.w);
                    ss += v.x * v.x + v.y * v.y + v.z * v.z + v.w * v.w;
                }
            }
            s  += __shfl_xor_sync(0xffffffffu, s, 1);
            ss += __shfl_xor_sync(0xffffffffu, ss, 1);
            s  += __shfl_xor_sync(0xffffffffu, s, 2);
            ss += __shfl_xor_sync(0xffffffffu, ss, 2);
            if (k == 0)
                g_part[(b * 16 + tile) * N_DIM + j] = make_float2(s, ss);
        }
        __threadfence();
        __syncthreads();
        if (tid == 0) atomicAdd(&g_cnt[b], 1u);

        // ---- Phase 2: wait for all 16 tiles of this batch ----
        while (ld_acq(&g_cnt[b]) < 16u) __nanosleep(64);

        // ---- Phase 3: energies from reduced partials ----
        if (tid < 64) {
            const float2* pp = g_part + b * 16 * N_DIM;
            float s = 0.f, ss = 0.f;
#pragma unroll
            for (int t = 0; t < 16; t++) {
                float2 p = pp[t * N_DIM + tid];
                s += p.x;
                ss += p.y;
            }
            float m = s * (1.f / T_DIM);
            e_s[tid] = fmaf(-m, m, ss * (1.f / T_DIM));
        }
        __syncthreads();

        // ---- Phase 4: rank-1 softmax weights into ws (3-pass, reg-light) ----
        if (tid < 64) {
            const float scale = 0.25f;
            float ei = e_s[tid];
            float mx = -1e30f;
#pragma unroll
            for (int j = 0; j < N_DIM; j++) {
                float v = scale * (ei * e_s[j] * c0 + ei * c1 + e_s[j] * c2 + c3);
                if (j == tid) v = -1e9f;
                mx = fmaxf(mx, v);
            }
            float sum = 0.f;
#pragma unroll
            for (int j = 0; j < N_DIM; j++) {
                float v = scale * (ei * e_s[j] * c0 + ei * c1 + e_s[j] * c2 + c3);
                if (j == tid) v = -1e9f;
                float w = __expf(v - mx);
                ws[tid * SW + j] = w;
                sum += w;
            }
            float inv = 1.f / sum;
#pragma unroll
            for (int j = 0; j < N_DIM; j++)
                ws[tid * SW + j] *= inv;
        }
        __syncthreads();

        // Tile 0 writes attn_w output (coalesced 512B per warp).
        if (tile == 0) {
            float* ao = attn_out + (size_t)b * N_DIM * N_DIM;
#pragma unroll
            for (int k = 0; k < 16; k++) {
                int f = tid * 16 + k;  // wait-free: each thread contiguous 16
                ao[f] = ws[(f >> 6) * SW + (f & 63)];
            }
        }

        // ---- Phase 5: A fragments (2 bands x 8 ksteps x 4 regs, rna cvt) ----
        uint32_t a[2][8][4];
#pragma unroll
        for (int band = 0; band < 2; band++) {
            int ib = i0 + band * 16;
#pragma unroll
            for (int ks = 0; ks < 8; ks++) {
                int j0 = ks * 8 + c;
                a[band][ks][0] = f2tf32(ws[(ib + r) * SW + j0]);
                a[band][ks][1] = f2tf32(ws[(ib + r + 8) * SW + j0]);
                a[band][ks][2] = f2tf32(ws[(ib + r) * SW + j0 + 4]);
                a[band][ks][3] = f2tf32(ws[(ib + r + 8) * SW + j0 + 4]);
            }
        }

        // ---- Phase 6: GEMM + residual; free each chunk for next batch ----
        float* ob = out + (size_t)b * N_DIM * T_DIM + (size_t)tile * TS;
        const float* xbn = x + (size_t)nb * N_DIM * T_DIM + (size_t)tile * TS;

#pragma unroll
        for (int ch = 0; ch < 4; ch++) {
            const float* xc = xs + ch * N_DIM * SBC;
#pragma unroll
            for (int nt = 0; nt < 2; nt++) {
                int t0 = tq * 16 + nt * 8;
                float d[2][4];
#pragma unroll
                for (int band = 0; band < 2; band++)
#pragma unroll
                    for (int q = 0; q < 4; q++) d[band][q] = 0.f;
#pragma unroll
                for (int ks = 0; ks < 8; ks++) {
                    uint32_t b0 = __float_as_uint(xc[(ks * 8 + c) * SBC + t0 + r]);
                    uint32_t b1 = __float_as_uint(xc[(ks * 8 + c + 4) * SBC + t0 + r]);
                    mma_tf32(d[0][0], d[0][1], d[0][2], d[0][3],
                             a[0][ks][0], a[0][ks][1], a[0][ks][2], a[0][ks][3], b0, b1);
                    mma_tf32(d[1][0], d[1][1], d[1][2], d[1][3],
                             a[1][ks][0], a[1][ks][1], a[1][ks][2], a[1][ks][3], b0, b1);
                }
                int tcol = t0 + 2 * c;
#pragma unroll
                for (int band = 0; band < 2; band++) {
                    int row0 = i0 + band * 16 + r, row1 = row0 + 8;
                    float2 res0 = *reinterpret_cast<const float2*>(xc + row0 * SBC + tcol);
                    float2 res1 = *reinterpret_cast<const float2*>(xc + row1 * SBC + tcol);
                    float2 o0 = make_float2(d[band][0] + res0.x, d[band][1] + res0.y);
                    float2 o1 = make_float2(d[band][2] + res1.x, d[band][3] + res1.y);
                    int tg = ch * CH + tcol;
                    *reinterpret_cast<float2*>(ob + (size_t)row0 * T_DIM + tg) = o0;
                    *reinterpret_cast<float2*>(ob + (size_t)row1 * T_DIM + tg) = o1;
                }
            }
            __syncthreads();  // all warps done with chunk ch
            if (nb < B_DIM) {
                float* xc2 = xs + ch * N_DIM * SBC;
#pragma unroll
                for (int k = 0; k < 4; k++) {
                    int f  = k * 256 + tid;
                    int jj = f >> 4;
                    int c4 = f & 15;
                    cp16(smem_u32(xc2 + jj * SBC + c4 * 4),
                         xbn + (size_t)jj * T_DIM + ch * CH + c4 * 4);
                }
                CP_COMMIT();
            }
        }
    }
}

extern "C" void kernel_launch(void* const* d_in, const int* in_sizes, int n_in,
                              void* d_out, int out_size) {
    const float* x  = (const float*)d_in[0];
    const float* Wq = (const float*)d_in[1];
    const float* bq = (const float*)d_in[2];
    const float* Wk = (const float*)d_in[3];
    const float* bk = (const float*)d_in[4];

    float* out = (float*)d_out;
    float* attn_out = out + (size_t)B_DIM * N_DIM * T_DIM;

    const int smem_bytes = (4 * N_DIM * SBC + N_DIM * SW + 64) * (int)sizeof(float);  // 91392
    cudaFuncSetAttribute(fused_kernel, cudaFuncAttributeMaxDynamicSharedMemorySize, smem_bytes);

    zero_kernel<<<1, B_DIM>>>();
    fused_kernel<<<SLOTS * 16, 256, smem_bytes>>>(x, Wq, bq, Wk, bk, out, attn_out);
}